// round 7
// baseline (speedup 1.0000x reference)
#include <cuda_runtime.h>
#include <cuda_bf16.h>

// PCEN: out = (E / (eps + M)^alpha + delta)^r - delta^r
// with causal EMA M_t = (1-s) M_{t-1} + s E_t, per (B,C) row over T.
//
// One block per row (B*C = 5120 rows), 512 threads, 8 elems/thread.
// Linear-recurrence parallel scan: thread-local scan -> warp shuffle scan
// (ratio A = a^8) -> serial 16-warp carry (ratio A^32 = a^256) -> recompute.
//
// CHUNK=8 (vs 16) cuts per-thread registers -> 3 blocks x 16 warps = 48
// warps/SM (75% occ, up from 59%): the R5 profile showed a latency-bound
// kernel (no pipe >46%, issue 52%), so occupancy is the lever.
//
// Smem: each 8-elem chunk = 3 float4 slots (2 data + 1 pad, 48B stride).
// All smem traffic is LDS.128/STS.128; 48B lane stride -> banks
// {0,12,24,4,16,28,8,20} per quarter-warp phase: conflict-free.
//
// r == 0.5f exactly for this module (log_r = inv_sigmoid(0.5) = 0), so u^r
// specializes to one MUFU.SQRT (runtime uniform check; __powf fallback kept).

#define T_LEN   4000
#define THREADS 512
#define CHUNK   8
#define NCHUNK  (T_LEN / CHUNK)   // 500
#define NVEC4   (T_LEN / 4)       // 1000
#define SLOT_STRIDE 3             // float4 slots per chunk
#define NSLOTS  (NCHUNK * SLOT_STRIDE)  // 1500 float4 = 24000 B
#define NWARP   (THREADS / 32)    // 16
#define EPS     1e-6f

__device__ __forceinline__ float sqrt_approx(float x) {
    float y;
    asm("sqrt.approx.f32 %0, %1;" : "=f"(y) : "f"(x));
    return y;
}

__global__ __launch_bounds__(THREADS, 3)
void pcen_kernel(const float* __restrict__ E,
                 const float* __restrict__ log_alpha,
                 const float* __restrict__ log_delta,
                 const float* __restrict__ log_r,
                 const float* __restrict__ log_s,
                 float* __restrict__ out,
                 int C)
{
    __shared__ float4 buf4[NSLOTS];
    __shared__ float warp_sum[NWARP];
    __shared__ float warp_pref[NWARP];

    const int row = blockIdx.x;            // b*C + c
    const int c   = row % C;
    const float4* e4 = (const float4*)(E   + (size_t)row * T_LEN);
    float4*       o4 = (float4*)      (out + (size_t)row * T_LEN);

    const int tid  = threadIdx.x;
    const int lane = tid & 31;
    const int wid  = tid >> 5;

    // --- per-channel params (redundant per thread; cheap) ---
    const float s     = 1.0f / (1.0f + __expf(-__ldg(&log_s[c])));
    const float a     = 1.0f - s;
    const float alpha = 1.0f / (1.0f + __expf(-__ldg(&log_alpha[c])));
    const float delta = __logf(1.0f + __expf(__ldg(&log_delta[c])));
    const float r     = 1.0f / (1.0f + __expf(-__ldg(&log_r[c])));
    const float dr    = __powf(delta, r);

    // --- coalesced float4 load into padded smem ---
    // float4 j -> chunk j>>1, pos j&1 -> slot (j>>1)*3 + (j&1) = j + (j>>1)
    #pragma unroll 2
    for (int j = tid; j < NVEC4; j += THREADS) {
        buf4[j + (j >> 1)] = __ldg(&e4[j]);
    }
    __syncthreads();

    // --- pass 1: thread-local scan over its 8-chunk (LDS.128, conflict-free) ---
    float ev[CHUNK];
    float local = 0.0f;
    const int slot = tid * SLOT_STRIDE;
    if (tid < NCHUNK) {
        #pragma unroll
        for (int q = 0; q < 2; q++) {
            float4 v = buf4[slot + q];
            ev[4*q + 0] = v.x;
            ev[4*q + 1] = v.y;
            ev[4*q + 2] = v.z;
            ev[4*q + 3] = v.w;
        }
        #pragma unroll
        for (int k = 0; k < CHUNK; k++) {
            local = a * local + s * ev[k];
        }
    }

    // A = a^8 (chunk ratio)
    float A = a * a;          // a^2
    A = A * A;                // a^4
    A = A * A;                // a^8

    // --- warp Hillis-Steele scan of p_i = A * p_{i-1} + local_i ---
    // Apow = A^lane built from the doubling w for free.
    float p = local;
    float w = A;              // A^(2^k)
    float Apow = 1.0f;        // A^lane
    #pragma unroll
    for (int d = 1; d < 32; d <<= 1) {
        float up = __shfl_up_sync(0xffffffffu, p, d);
        if (lane >= d) p += w * up;
        if (lane & d)  Apow *= w;
        w = w * w;
    }
    const float A32 = w;      // A^32 = a^256 (per-warp ratio)

    // exclusive prefix within warp
    float pe = __shfl_up_sync(0xffffffffu, p, 1);
    if (lane == 0) pe = 0.0f;

    if (lane == 31) warp_sum[wid] = p;
    __syncthreads();

    // serial carry across the 16 warps (ratio A32), exclusive
    if (tid == 0) {
        float acc = 0.0f;
        #pragma unroll
        for (int j = 0; j < NWARP; j++) {
            warp_pref[j] = acc;
            acc = A32 * acc + warp_sum[j];
        }
    }
    __syncthreads();

    // --- pass 2: recompute with true incoming state, apply PCEN math ---
    if (tid < NCHUNK) {
        float m = Apow * warp_pref[wid] + pe;   // M state before this chunk
        if (r == 0.5f) {
            #pragma unroll
            for (int k = 0; k < CHUNK; k++) {
                m = a * m + s * ev[k];
                float x  = EPS + m;
                float pw = __powf(x, -alpha);    // LG2+EX2
                float u  = ev[k] * pw + delta;
                ev[k]    = sqrt_approx(u) - dr;  // u^0.5: single MUFU.SQRT
            }
        } else {
            #pragma unroll
            for (int k = 0; k < CHUNK; k++) {
                m = a * m + s * ev[k];
                float x  = EPS + m;
                float pw = __powf(x, -alpha);
                float u  = ev[k] * pw + delta;
                ev[k]    = __powf(u, r) - dr;
            }
        }
        // write results back via STS.128 (conflict-free)
        #pragma unroll
        for (int q = 0; q < 2; q++) {
            float4 v;
            v.x = ev[4*q + 0];
            v.y = ev[4*q + 1];
            v.z = ev[4*q + 2];
            v.w = ev[4*q + 3];
            buf4[slot + q] = v;
        }
    }
    __syncthreads();

    // --- coalesced float4 store ---
    #pragma unroll 2
    for (int j = tid; j < NVEC4; j += THREADS) {
        o4[j] = buf4[j + (j >> 1)];
    }
}

extern "C" void kernel_launch(void* const* d_in, const int* in_sizes, int n_in,
                              void* d_out, int out_size)
{
    const float* E         = (const float*)d_in[0];
    const float* log_alpha = (const float*)d_in[1];
    const float* log_delta = (const float*)d_in[2];
    const float* log_r     = (const float*)d_in[3];
    const float* log_s     = (const float*)d_in[4];
    float*       out       = (float*)d_out;

    const int C    = in_sizes[1];
    const int rows = in_sizes[0] / T_LEN;   // B*C

    pcen_kernel<<<rows, THREADS>>>(E, log_alpha, log_delta, log_r, log_s, out, C);
}

// round 9
// speedup vs baseline: 1.4211x; 1.4211x over previous
#include <cuda_runtime.h>
#include <cuda_bf16.h>

// PCEN: out = (E / (eps + M)^alpha + delta)^r - delta^r
// with causal EMA M_t = (1-s) M_{t-1} + s E_t, per (B,C) row over T.
//
// R7 post-mortem: occupancy was NOT the lever (occ 59->69% regressed dur).
// Profile invariant across variants: no unit >46%, issue ~55% -> cost is
// instruction volume + phase structure, mostly smem-staging machinery and
// per-thread redundant parameter math. This version removes both:
//   * no data staging: each thread LDG.128s its own 16-elem chunk straight
//     into registers (warp reads 2KB dense), scans in registers, STG.128s
//     results directly. Only the 8-word warp-carry arrays live in smem.
//   * per-channel params (sigmoid/softplus/pow: ~10 MUFU each) computed once
//     by a tiny prep kernel into a __device__ table; main kernel just loads.
//
// Scan: thread-local (16) -> warp shuffle scan (ratio A=a^16) -> serial
// 8-warp carry (ratio A^32) -> recompute with true incoming state.
//
// r == 0.5f exactly here (log_r = inv_sigmoid(0.5) = 0) -> u^r is one
// MUFU.SQRT (uniform runtime check; __powf fallback kept).

#define T_LEN   4000
#define THREADS 256
#define CHUNK   16
#define NCHUNK  (T_LEN / CHUNK)   // 250
#define NWARP   (THREADS / 32)    // 8
#define EPS     1e-6f
#define MAX_C   1024

// per-channel: {s, a, -alpha, delta, dr, r, pad, pad}
__device__ float g_param_tab[MAX_C * 8];

__device__ __forceinline__ float sqrt_approx(float x) {
    float y;
    asm("sqrt.approx.f32 %0, %1;" : "=f"(y) : "f"(x));
    return y;
}

__global__ void pcen_prep(const float* __restrict__ log_alpha,
                          const float* __restrict__ log_delta,
                          const float* __restrict__ log_r,
                          const float* __restrict__ log_s,
                          int C)
{
    int c = blockIdx.x * blockDim.x + threadIdx.x;
    if (c < C) {
        float s     = 1.0f / (1.0f + __expf(-log_s[c]));
        float alpha = 1.0f / (1.0f + __expf(-log_alpha[c]));
        float delta = __logf(1.0f + __expf(log_delta[c]));
        float r     = 1.0f / (1.0f + __expf(-log_r[c]));
        float dr    = __powf(delta, r);
        float* p = &g_param_tab[c * 8];
        p[0] = s;
        p[1] = 1.0f - s;
        p[2] = -alpha;
        p[3] = delta;
        p[4] = dr;
        p[5] = r;
    }
}

__global__ __launch_bounds__(THREADS)
void pcen_kernel(const float* __restrict__ E,
                 float* __restrict__ out,
                 int C)
{
    __shared__ float warp_sum[NWARP];
    __shared__ float warp_pref[NWARP];

    const int row = blockIdx.x;            // b*C + c
    const int c   = row % C;

    const int tid  = threadIdx.x;
    const int lane = tid & 31;
    const int wid  = tid >> 5;

    // --- per-channel params from table (cached, broadcast) ---
    const float4 P0 = *(const float4*)&g_param_tab[c * 8];
    const float2 P1 = *(const float2*)&g_param_tab[c * 8 + 4];
    const float s      = P0.x;
    const float a      = P0.y;
    const float nalpha = P0.z;   // -alpha
    const float delta  = P0.w;
    const float dr     = P1.x;
    const float r      = P1.y;

    // --- direct register load: thread t owns elements [t*16, t*16+16) ---
    float ev[CHUNK];
    float local = 0.0f;
    const bool active = (tid < NCHUNK);
    const float4* src = (const float4*)(E + (size_t)row * T_LEN) + tid * 4;
    if (active) {
        float4 v0 = __ldg(src + 0);
        float4 v1 = __ldg(src + 1);
        float4 v2 = __ldg(src + 2);
        float4 v3 = __ldg(src + 3);
        ev[0]=v0.x;  ev[1]=v0.y;  ev[2]=v0.z;  ev[3]=v0.w;
        ev[4]=v1.x;  ev[5]=v1.y;  ev[6]=v1.z;  ev[7]=v1.w;
        ev[8]=v2.x;  ev[9]=v2.y;  ev[10]=v2.z; ev[11]=v2.w;
        ev[12]=v3.x; ev[13]=v3.y; ev[14]=v3.z; ev[15]=v3.w;
        #pragma unroll
        for (int k = 0; k < CHUNK; k++) {
            local = __fmaf_rn(a, local, s * ev[k]);
        }
    }

    // A = a^16 (chunk ratio)
    float A = a * a;          // a^2
    A = A * A;                // a^4
    A = A * A;                // a^8
    A = A * A;                // a^16

    // --- warp Hillis-Steele scan of p_i = A * p_{i-1} + local_i ---
    // Apow = A^lane built from the doubling w for free.
    float p = local;
    float w = A;              // A^(2^k)
    float Apow = 1.0f;        // A^lane
    #pragma unroll
    for (int d = 1; d < 32; d <<= 1) {
        float up = __shfl_up_sync(0xffffffffu, p, d);
        if (lane >= d) p += w * up;
        if (lane & d)  Apow *= w;
        w = w * w;
    }
    const float A32 = w;      // A^32

    // exclusive prefix within warp
    float pe = __shfl_up_sync(0xffffffffu, p, 1);
    if (lane == 0) pe = 0.0f;

    if (lane == 31) warp_sum[wid] = p;
    __syncthreads();

    // serial carry across the 8 warps (ratio A32), exclusive
    if (tid == 0) {
        float acc = 0.0f;
        #pragma unroll
        for (int j = 0; j < NWARP; j++) {
            warp_pref[j] = acc;
            acc = __fmaf_rn(A32, acc, warp_sum[j]);
        }
    }
    __syncthreads();

    // --- pass 2: recompute with true incoming state, apply PCEN math,
    //     store straight from registers ---
    if (active) {
        float m = __fmaf_rn(Apow, warp_pref[wid], pe);  // M before this chunk
        if (r == 0.5f) {
            #pragma unroll
            for (int k = 0; k < CHUNK; k++) {
                m = __fmaf_rn(a, m, s * ev[k]);
                float x  = EPS + m;
                float pw = __expf(nalpha * __logf(x));  // x^{-alpha}
                float u  = __fmaf_rn(ev[k], pw, delta);
                ev[k]    = sqrt_approx(u) - dr;         // u^0.5
            }
        } else {
            #pragma unroll
            for (int k = 0; k < CHUNK; k++) {
                m = __fmaf_rn(a, m, s * ev[k]);
                float x  = EPS + m;
                float pw = __powf(x, nalpha);
                float u  = __fmaf_rn(ev[k], pw, delta);
                ev[k]    = __powf(u, r) - dr;
            }
        }
        float4* dst = (float4*)(out + (size_t)row * T_LEN) + tid * 4;
        float4 o0 = {ev[0],  ev[1],  ev[2],  ev[3]};
        float4 o1 = {ev[4],  ev[5],  ev[6],  ev[7]};
        float4 o2 = {ev[8],  ev[9],  ev[10], ev[11]};
        float4 o3 = {ev[12], ev[13], ev[14], ev[15]};
        dst[0] = o0;
        dst[1] = o1;
        dst[2] = o2;
        dst[3] = o3;
    }
}

extern "C" void kernel_launch(void* const* d_in, const int* in_sizes, int n_in,
                              void* d_out, int out_size)
{
    const float* E         = (const float*)d_in[0];
    const float* log_alpha = (const float*)d_in[1];
    const float* log_delta = (const float*)d_in[2];
    const float* log_r     = (const float*)d_in[3];
    const float* log_s     = (const float*)d_in[4];
    float*       out       = (float*)d_out;

    const int C    = in_sizes[1];
    const int rows = in_sizes[0] / T_LEN;   // B*C

    pcen_prep<<<(C + 63) / 64, 64>>>(log_alpha, log_delta, log_r, log_s, C);
    pcen_kernel<<<rows, THREADS>>>(E, out, C);
}